// round 2
// baseline (speedup 1.0000x reference)
#include <cuda_runtime.h>

#define N_NODES 100000
#define N_EDGES 1600000
#define HIDDEN_DIM 64
#define EIGS_DIM 32

// Scratch (device globals: no allocation allowed in kernel_launch)
__device__ float g_e[N_EDGES];       // per-edge numerator e = clip(exp(s),-5,5)
__device__ float g_denom[N_NODES];   // per-node segment sum of e

// ---------------------------------------------------------------------------
// Pass 1: per-edge logits + denominator accumulation.
// 8 threads per edge. Lane j handles q/k dims [8j,8j+8) and eigs dims [4j,4j+4).
// ---------------------------------------------------------------------------
__global__ void pass1_kernel(const float* __restrict__ q,
                             const float* __restrict__ k,
                             const float* __restrict__ eigs,
                             const float* __restrict__ lambda0,
                             const int* __restrict__ idx)
{
    int gid  = blockIdx.x * blockDim.x + threadIdx.x;
    int edge = gid >> 3;
    if (edge >= N_EDGES) return;
    int lane = gid & 7;

    int i0 = idx[edge];            // destination (row) node
    int i1 = idx[N_EDGES + edge];  // source (col) node

    const float4* q4 = (const float4*)q + (size_t)i0 * (HIDDEN_DIM / 4);
    const float4* k4 = (const float4*)k + (size_t)i1 * (HIDDEN_DIM / 4);

    float4 a0 = q4[lane * 2];
    float4 a1 = q4[lane * 2 + 1];
    float4 b0 = k4[lane * 2];
    float4 b1 = k4[lane * 2 + 1];

    float x = a0.x * b0.x + a0.y * b0.y + a0.z * b0.z + a0.w * b0.w
            + a1.x * b1.x + a1.y * b1.y + a1.z * b1.z + a1.w * b1.w;

    float4 ea = ((const float4*)eigs)[(size_t)i0 * (EIGS_DIM / 4) + lane];
    float4 eb = ((const float4*)eigs)[(size_t)i1 * (EIGS_DIM / 4) + lane];
    float y = ea.x * eb.x + ea.y * eb.y + ea.z * eb.z + ea.w * eb.w;

    float lam = expf(lambda0[0]);
    // inv_sqrt_dim = 1/sqrt(64) = 0.125
    float t = x * 0.125f + lam * y;

    // 8-lane butterfly reduction (xor offsets < 8 stay within the group)
    t += __shfl_xor_sync(0xffffffffu, t, 1);
    t += __shfl_xor_sync(0xffffffffu, t, 2);
    t += __shfl_xor_sync(0xffffffffu, t, 4);

    if (lane == 0) {
        // clip(exp(s), -5, 5): exp >= 0 so only upper bound binds
        float e = fminf(expf(t), 5.0f);
        g_e[edge] = e;
        atomicAdd(&g_denom[i0], e);
    }
}

// ---------------------------------------------------------------------------
// Pass 2: out[i0] += (e/denom[i0]) * v[i1]
// 16 threads per edge; each lane handles 4 output dims via one vector RED.
// ---------------------------------------------------------------------------
__global__ void pass2_kernel(const float* __restrict__ v,
                             const int* __restrict__ idx,
                             float* __restrict__ out)
{
    int gid  = blockIdx.x * blockDim.x + threadIdx.x;
    int edge = gid >> 4;
    if (edge >= N_EDGES) return;
    int lane = gid & 15;

    int i0 = idx[edge];
    int i1 = idx[N_EDGES + edge];

    float den = g_denom[i0];
    den = (den == 0.0f) ? 1.0f : den;
    float w = g_e[edge] / den;

    float4 vv = ((const float4*)v)[(size_t)i1 * (HIDDEN_DIM / 4) + lane];
    float rx = vv.x * w, ry = vv.y * w, rz = vv.z * w, rw = vv.w * w;

    float* dst = out + (size_t)i0 * HIDDEN_DIM + lane * 4;
    asm volatile("red.global.add.v4.f32 [%0], {%1, %2, %3, %4};"
                 :: "l"(dst), "f"(rx), "f"(ry), "f"(rz), "f"(rw)
                 : "memory");
}

extern "C" void kernel_launch(void* const* d_in, const int* in_sizes, int n_in,
                              void* d_out, int out_size)
{
    const float* q       = (const float*)d_in[0];
    const float* k       = (const float*)d_in[1];
    const float* v       = (const float*)d_in[2];
    const float* eigs    = (const float*)d_in[3];
    const float* lambda0 = (const float*)d_in[4];
    const int*   idx     = (const int*)d_in[5];

    void* denom_ptr = nullptr;
    cudaGetSymbolAddress(&denom_ptr, g_denom);

    cudaMemsetAsync(denom_ptr, 0, N_NODES * sizeof(float));
    cudaMemsetAsync(d_out, 0, (size_t)out_size * sizeof(float));

    {
        long long total = (long long)N_EDGES * 8;
        int block = 256;
        int grid = (int)((total + block - 1) / block);
        pass1_kernel<<<grid, block>>>(q, k, eigs, lambda0, idx);
    }
    {
        long long total = (long long)N_EDGES * 16;
        int block = 256;
        int grid = (int)((total + block - 1) / block);
        pass2_kernel<<<grid, block>>>(v, idx, (float*)d_out);
    }
}